// round 7
// baseline (speedup 1.0000x reference)
#include <cuda_runtime.h>
#include <cuda_bf16.h>

// wACSFRad R7: culling bucket-CSR.
//  pack:    xyzw[i]=(x,y,z,float(z_i)); cursor[i]=0
//  scatter: 4 edges/thread; cull rij>=8 or s==0 (fc==0 kills ~57% of edges);
//           bucket[recv*CAP + atomicAdd(cursor)] = (rij, s)
//  compute: 4 lanes/node; bucket read as float4 (2 edges per LDG.128),
//           per-lane register (eta,mu,acc), plain coalesced store.
//
// Inputs: z i32[100000], xyz f32[100000,3], eij i32[3200000,2], eta_mu f32[118,22,2]
// Output: f32 [100000,22]

#define N_NODES_MAX 100000
#define N_TYPES 118
#define N_PARAMS 22
#define CAP 64                  // surviving degree ~Binom(32,0.43), max≈40
#define PI_OVER_CUT 0.39269908169872414f

__device__ float4 g_xyzw[N_NODES_MAX];
__device__ int    g_cursor[N_NODES_MAX];
__device__ __align__(16) float2 g_bucket[(long long)N_NODES_MAX * CAP]; // (rij,s)

__global__ void pack_nodes_kernel(const int* __restrict__ z,
                                  const float* __restrict__ xyz, int n) {
    int i = blockIdx.x * blockDim.x + threadIdx.x;
    if (i < n) {
        float4 v;
        v.x = xyz[3 * i + 0];
        v.y = xyz[3 * i + 1];
        v.z = xyz[3 * i + 2];
        v.w = (float)z[i];          // exact for 0..117; weight AND type
        g_xyzw[i] = v;
        g_cursor[i] = 0;
    }
}

__device__ __forceinline__ void scatter_one(int recv, int send,
                                            const float2* __restrict__ eta_mu2,
                                            float* __restrict__ out) {
    const float4 a = __ldg(&g_xyzw[recv]);
    const float4 b = __ldg(&g_xyzw[send]);
    const float dx = a.x - b.x, dy = a.y - b.y, dz = a.z - b.z;
    const float r2 = fmaf(dx, dx, fmaf(dy, dy, dz * dz));
    if (r2 >= 64.0f) return;                       // fc == 0: dead edge
    const float rij = sqrtf(r2);
    const float s = 0.5f * (__cosf(rij * PI_OVER_CUT) + 1.0f) * b.w;
    if (s == 0.0f) return;                         // w == 0 senders

    const int pos = atomicAdd(&g_cursor[recv], 1);
    if (pos < CAP) {
        g_bucket[(long long)recv * CAP + pos] = make_float2(rij, s);
    } else {
        // overflow fallback (never taken at these degrees, but correct)
        const int t = (int)a.w;
        float* o = out + (long long)recv * N_PARAMS;
        for (int k = 0; k < N_PARAMS; k++) {
            const float2 p = __ldg(&eta_mu2[t * N_PARAMS + k]);
            const float d = rij - p.y;
            atomicAdd(o + k, s * __expf(-p.x * d * d));
        }
    }
}

__global__ void __launch_bounds__(256) scatter_kernel(
    const int4* __restrict__ eij2,        // 2 edges per int4
    const int2* __restrict__ eij,
    const float2* __restrict__ eta_mu2,
    float* __restrict__ out,
    int n_quads, int n_edges)
{
    const int i = blockIdx.x * blockDim.x + threadIdx.x;
    if (i < n_quads) {
        // 4 edges per thread: deeper MLP across the gather->atomic->store chain
        const int4 v0 = __ldg(&eij2[2 * i]);
        const int4 v1 = __ldg(&eij2[2 * i + 1]);
        scatter_one(v0.x, v0.y, eta_mu2, out);
        scatter_one(v0.z, v0.w, eta_mu2, out);
        scatter_one(v1.x, v1.y, eta_mu2, out);
        scatter_one(v1.z, v1.w, eta_mu2, out);
    }
    if (i == 0) {                          // tail: up to 3 edges
        for (int e = n_quads * 4; e < n_edges; e++) {
            const int2 t = __ldg(&eij[e]);
            scatter_one(t.x, t.y, eta_mu2, out);
        }
    }
}

__global__ void __launch_bounds__(256) compute_kernel(
    const float2* __restrict__ eta_mu2,
    float* __restrict__ out,
    int n_nodes)
{
    __shared__ float2 tbl[N_TYPES * N_PARAMS];     // 20768 B
    for (int i = threadIdx.x; i < N_TYPES * N_PARAMS; i += blockDim.x)
        tbl[i] = eta_mu2[i];
    __syncthreads();

    const int gid = blockIdx.x * blockDim.x + threadIdx.x;
    int node = gid >> 2;
    const int r = gid & 3;
    if (node >= n_nodes) node = n_nodes - 1;       // benign duplicate work

    const float4 a = __ldg(&g_xyzw[node]);
    const int t = (int)a.w;
    const int deg_raw = g_cursor[node];
    const int deg = deg_raw < CAP ? deg_raw : CAP;
    const float4* __restrict__ bkt4 =
        reinterpret_cast<const float4*>(g_bucket + (long long)node * CAP);

    // lane r owns params k = r, r+4, ... (6 slots; last 2 of lanes 2,3 unused)
    float eta[6], mu[6];
    #pragma unroll
    for (int j = 0; j < 6; j++) {
        const int k = r + 4 * j;
        const int kk = k < N_PARAMS ? k : (N_PARAMS - 1);
        const float2 p = tbl[t * N_PARAMS + kk];
        eta[j] = p.x; mu[j] = p.y;
    }
    float acc[6] = {0.f, 0.f, 0.f, 0.f, 0.f, 0.f};

    // 2 edges per LDG.128 (group-uniform address -> L1 broadcast, 1 wf)
    const int npair = deg >> 1;
    #pragma unroll 2
    for (int p = 0; p < npair; p++) {
        const float4 v = __ldg(&bkt4[p]);          // (r1, s1, r2, s2)
        #pragma unroll
        for (int q = 0; q < 6; q++) {
            const float d1 = v.x - mu[q];
            const float d2 = v.z - mu[q];
            acc[q] = fmaf(v.y, __expf(-eta[q] * d1 * d1), acc[q]);
            acc[q] = fmaf(v.w, __expf(-eta[q] * d2 * d2), acc[q]);
        }
    }
    if (deg & 1) {
        const float2 rs = __ldg(&((const float2*)bkt4)[deg - 1]);
        #pragma unroll
        for (int q = 0; q < 6; q++) {
            const float d = rs.x - mu[q];
            acc[q] = fmaf(rs.y, __expf(-eta[q] * d * d), acc[q]);
        }
    }

    float* o = out + (long long)node * N_PARAMS;
    if (deg_raw <= CAP) {
        #pragma unroll
        for (int j = 0; j < 6; j++) {
            const int k = r + 4 * j;
            if (k < N_PARAMS) o[k] = acc[j];
        }
    } else {
        #pragma unroll
        for (int j = 0; j < 6; j++) {
            const int k = r + 4 * j;
            if (k < N_PARAMS) atomicAdd(o + k, acc[j]);
        }
    }
}

extern "C" void kernel_launch(void* const* d_in, const int* in_sizes, int n_in,
                              void* d_out, int out_size) {
    const int*    z       = (const int*)   d_in[0];
    const float*  xyz     = (const float*) d_in[1];
    const int2*   eij     = (const int2*)  d_in[2];
    const int4*   eij2    = (const int4*)  d_in[2];
    const float2* eta_mu2 = (const float2*)d_in[3];
    float*        out     = (float*)d_out;

    const int n_nodes = in_sizes[0];
    const int n_edges = in_sizes[2] / 2;
    const int n_quads = n_edges / 4;

    cudaMemsetAsync(d_out, 0, (size_t)out_size * sizeof(float), 0);

    pack_nodes_kernel<<<(n_nodes + 255) / 256, 256>>>(z, xyz, n_nodes);
    scatter_kernel<<<(n_quads + 255) / 256, 256>>>(eij2, eij, eta_mu2, out,
                                                   n_quads, n_edges);

    const int threads_needed = n_nodes * 4;
    compute_kernel<<<(threads_needed + 255) / 256, 256>>>(eta_mu2, out, n_nodes);
}

// round 8
// speedup vs baseline: 1.0354x; 1.0354x over previous
#include <cuda_runtime.h>
#include <cuda_bf16.h>

// wACSFRad R8: culling bucket-CSR, no output memset.
//  pack:    4 nodes/thread vectorized; xyzw=(x,y,z,float(type)); cursor=0;
//           ovf_count=0
//  scatter: 2 edges/thread; cull r2>=64 (fc==0, ~57% of edges) and s==0;
//           bucket[recv*CAP + atomicAdd(cursor)] = (rij, s); CAP overflow
//           goes to a static list (never in practice, correct always)
//  compute: 4 lanes/node; float4 bucket reads (2 edges/LDG, group-broadcast);
//           per-lane register (e2=-eta*log2e, mu); ex2.approx; PLAIN stores.
//  fixup:   merges overflow list with atomics (instant no-op when empty).
//
// Inputs: z i32[100000], xyz f32[100000,3], eij i32[3200000,2], eta_mu f32[118,22,2]
// Output: f32 [100000,22]

#define N_NODES_MAX 100000
#define N_TYPES 118
#define N_PARAMS 22
#define CAP 64                   // surviving degree ~Poisson(13.8), max≈40
#define OVF_CAP 3200000          // bulletproof: can hold every edge
#define PI_OVER_CUT 0.39269908169872414f
#define LOG2E 1.4426950408889634f

__device__ float4 g_xyzw[N_NODES_MAX];
__device__ int    g_cursor[N_NODES_MAX];
__device__ __align__(16) float2 g_bucket[(long long)N_NODES_MAX * CAP]; // (rij,s)
__device__ int    g_ovf_count;
__device__ int    g_ovf_recv[OVF_CAP];
__device__ float2 g_ovf_rs[OVF_CAP];

__device__ __forceinline__ float ex2(float x) {
    float r;
    asm("ex2.approx.f32 %0, %1;" : "=f"(r) : "f"(x));
    return r;
}

__global__ void pack_nodes_kernel(const int4* __restrict__ z4,
                                  const float4* __restrict__ xyz4, int n4) {
    const int i = blockIdx.x * blockDim.x + threadIdx.x;   // group of 4 nodes
    if (i < n4) {
        const float4 a = __ldg(&xyz4[3 * i + 0]);
        const float4 b = __ldg(&xyz4[3 * i + 1]);
        const float4 c = __ldg(&xyz4[3 * i + 2]);
        const int4  zz = __ldg(&z4[i]);
        g_xyzw[4 * i + 0] = make_float4(a.x, a.y, a.z, (float)zz.x);
        g_xyzw[4 * i + 1] = make_float4(a.w, b.x, b.y, (float)zz.y);
        g_xyzw[4 * i + 2] = make_float4(b.z, b.w, c.x, (float)zz.z);
        g_xyzw[4 * i + 3] = make_float4(c.y, c.z, c.w, (float)zz.w);
        *reinterpret_cast<int4*>(&g_cursor[4 * i]) = make_int4(0, 0, 0, 0);
    }
    if (i == 0) g_ovf_count = 0;
}

__device__ __forceinline__ void scatter_one(int recv, int send) {
    const float4 a = __ldg(&g_xyzw[recv]);
    const float4 b = __ldg(&g_xyzw[send]);
    const float dx = a.x - b.x, dy = a.y - b.y, dz = a.z - b.z;
    const float r2 = fmaf(dx, dx, fmaf(dy, dy, dz * dz));
    if (r2 >= 64.0f) return;                       // fc == 0: dead edge
    const float rij = sqrtf(r2);
    const float s = 0.5f * (__cosf(rij * PI_OVER_CUT) + 1.0f) * b.w;
    if (s == 0.0f) return;                         // w == 0 senders

    const int pos = atomicAdd(&g_cursor[recv], 1);
    if (pos < CAP) {
        g_bucket[(long long)recv * CAP + pos] = make_float2(rij, s);
    } else {                                       // never at these degrees
        const int o = atomicAdd(&g_ovf_count, 1);
        if (o < OVF_CAP) {
            g_ovf_recv[o] = recv;
            g_ovf_rs[o] = make_float2(rij, s);
        }
    }
}

__global__ void __launch_bounds__(256) scatter_kernel(
    const int4* __restrict__ eij2,        // 2 edges per int4
    const int2* __restrict__ eij,
    int n_pairs, int n_edges)
{
    const int i = blockIdx.x * blockDim.x + threadIdx.x;
    if (i < n_pairs) {
        const int4 v = __ldg(&eij2[i]);
        scatter_one(v.x, v.y);
        scatter_one(v.z, v.w);
    }
    if (i == 0 && (n_edges & 1)) {
        const int2 t = __ldg(&eij[n_edges - 1]);
        scatter_one(t.x, t.y);
    }
}

__global__ void __launch_bounds__(256) compute_kernel(
    const float2* __restrict__ eta_mu2,
    float* __restrict__ out,
    int n_nodes)
{
    // staged table, eta prescaled: (e2 = -eta*log2e, mu). 20768 B
    __shared__ float2 tbl[N_TYPES * N_PARAMS];
    for (int i = threadIdx.x; i < N_TYPES * N_PARAMS; i += blockDim.x) {
        const float2 p = eta_mu2[i];
        tbl[i] = make_float2(-p.x * LOG2E, p.y);
    }
    __syncthreads();

    const int gid = blockIdx.x * blockDim.x + threadIdx.x;
    int node = gid >> 2;
    const int r = gid & 3;
    if (node >= n_nodes) node = n_nodes - 1;       // benign duplicate work

    const float4 a = __ldg(&g_xyzw[node]);
    const int t = (int)a.w;
    int deg = g_cursor[node];
    deg = deg < CAP ? deg : CAP;                   // overflow handled by fixup
    const float4* __restrict__ bkt4 =
        reinterpret_cast<const float4*>(g_bucket + (long long)node * CAP);

    // lane r owns params k = r, r+4, ... (6 slots; 2 padded in lanes 2,3)
    float e2[6], mu[6];
    #pragma unroll
    for (int j = 0; j < 6; j++) {
        const int k = r + 4 * j;
        const int kk = k < N_PARAMS ? k : (N_PARAMS - 1);
        const float2 p = tbl[t * N_PARAMS + kk];
        e2[j] = p.x; mu[j] = p.y;
    }
    float acc[6] = {0.f, 0.f, 0.f, 0.f, 0.f, 0.f};

    const int npair = deg >> 1;
    #pragma unroll 2
    for (int p = 0; p < npair; p++) {
        const float4 v = __ldg(&bkt4[p]);          // (r1, s1, r2, s2)
        #pragma unroll
        for (int q = 0; q < 6; q++) {
            const float d1 = v.x - mu[q];
            const float d2 = v.z - mu[q];
            acc[q] = fmaf(v.y, ex2((e2[q] * d1) * d1), acc[q]);
            acc[q] = fmaf(v.w, ex2((e2[q] * d2) * d2), acc[q]);
        }
    }
    if (deg & 1) {
        const float2 rs =
            __ldg(&reinterpret_cast<const float2*>(bkt4)[deg - 1]);
        #pragma unroll
        for (int q = 0; q < 6; q++) {
            const float d = rs.x - mu[q];
            acc[q] = fmaf(rs.y, ex2((e2[q] * d) * d), acc[q]);
        }
    }

    float* o = out + (long long)node * N_PARAMS;
    #pragma unroll
    for (int j = 0; j < 6; j++) {
        const int k = r + 4 * j;
        if (k < N_PARAMS) o[k] = acc[j];           // plain coalesced store
    }
}

// Merge CAP-overflow edges (normally zero) on top of the plain-stored output.
__global__ void fixup_kernel(const float2* __restrict__ eta_mu2,
                             float* __restrict__ out)
{
    int count = g_ovf_count;
    if (count > OVF_CAP) count = OVF_CAP;
    const int stride = gridDim.x * blockDim.x;
    for (int i = blockIdx.x * blockDim.x + threadIdx.x; i < count; i += stride) {
        const int recv = g_ovf_recv[i];
        const float2 rs = g_ovf_rs[i];
        const int t = (int)__ldg(&g_xyzw[recv].w);
        float* o = out + (long long)recv * N_PARAMS;
        for (int k = 0; k < N_PARAMS; k++) {
            const float2 p = __ldg(&eta_mu2[t * N_PARAMS + k]);
            const float d = rs.x - p.y;
            atomicAdd(o + k, rs.y * __expf(-p.x * d * d));
        }
    }
}

extern "C" void kernel_launch(void* const* d_in, const int* in_sizes, int n_in,
                              void* d_out, int out_size) {
    const int4*   z4      = (const int4*)  d_in[0];
    const float4* xyz4    = (const float4*)d_in[1];
    const int2*   eij     = (const int2*)  d_in[2];
    const int4*   eij2    = (const int4*)  d_in[2];
    const float2* eta_mu2 = (const float2*)d_in[3];
    float*        out     = (float*)d_out;

    const int n_nodes = in_sizes[0];        // 100000, divisible by 4
    const int n4 = n_nodes / 4;
    const int n_edges = in_sizes[2] / 2;
    const int n_pairs = n_edges / 2;

    pack_nodes_kernel<<<(n4 + 255) / 256, 256>>>(z4, xyz4, n4);
    scatter_kernel<<<(n_pairs + 255) / 256, 256>>>(eij2, eij, n_pairs, n_edges);

    const int threads_needed = n_nodes * 4;
    compute_kernel<<<(threads_needed + 255) / 256, 256>>>(eta_mu2, out, n_nodes);
    fixup_kernel<<<64, 256>>>(eta_mu2, out);
}

// round 9
// speedup vs baseline: 1.0637x; 1.0274x over previous
#include <cuda_runtime.h>
#include <cuda_bf16.h>

// wACSFRad R9: culling bucket-CSR, 3 kernels, no fixup launch.
//  pack:    4 nodes/thread vectorized; xyzw=(x,y,z,float(type)); cursor=0
//  scatter: 2 edges/thread; cull r2>=64 (fc==0, ~57% of edges) and s==0;
//           bucket[recv*CAP + atomicAdd(cursor)] = (rij, s); CAP overflow
//           goes to a static list (never in practice, correct always)
//  compute: 4 lanes/node; float4 bucket reads (2 edges/LDG, group-broadcast);
//           per-lane register (e2=-eta*log2e, mu); ex2.approx; PLAIN stores;
//           overflow entries folded in by an in-kernel (never-taken) scan.
//
// Inputs: z i32[100000], xyz f32[100000,3], eij i32[3200000,2], eta_mu f32[118,22,2]
// Output: f32 [100000,22]

#define N_NODES_MAX 100000
#define N_TYPES 118
#define N_PARAMS 22
#define CAP 64                   // surviving degree ~Poisson(13.8), max≈40
#define OVF_CAP 3200000          // bulletproof: can hold every edge
#define PI_OVER_CUT 0.39269908169872414f
#define LOG2E 1.4426950408889634f

__device__ float4 g_xyzw[N_NODES_MAX];
__device__ int    g_cursor[N_NODES_MAX];
__device__ __align__(16) float2 g_bucket[(long long)N_NODES_MAX * CAP]; // (rij,s)
__device__ int    g_ovf_count;
__device__ int    g_ovf_recv[OVF_CAP];
__device__ float2 g_ovf_rs[OVF_CAP];

__device__ __forceinline__ float ex2(float x) {
    float r;
    asm("ex2.approx.f32 %0, %1;" : "=f"(r) : "f"(x));
    return r;
}

__global__ void pack_nodes_kernel(const int4* __restrict__ z4,
                                  const float4* __restrict__ xyz4, int n4) {
    const int i = blockIdx.x * blockDim.x + threadIdx.x;   // group of 4 nodes
    if (i < n4) {
        // all loads first: independent chains, better MLP in the single wave
        const float4 a = __ldg(&xyz4[3 * i + 0]);
        const float4 b = __ldg(&xyz4[3 * i + 1]);
        const float4 c = __ldg(&xyz4[3 * i + 2]);
        const int4  zz = __ldg(&z4[i]);
        float4 o0 = make_float4(a.x, a.y, a.z, (float)zz.x);
        float4 o1 = make_float4(a.w, b.x, b.y, (float)zz.y);
        float4 o2 = make_float4(b.z, b.w, c.x, (float)zz.z);
        float4 o3 = make_float4(c.y, c.z, c.w, (float)zz.w);
        g_xyzw[4 * i + 0] = o0;
        g_xyzw[4 * i + 1] = o1;
        g_xyzw[4 * i + 2] = o2;
        g_xyzw[4 * i + 3] = o3;
        *reinterpret_cast<int4*>(&g_cursor[4 * i]) = make_int4(0, 0, 0, 0);
    }
    if (i == 0) g_ovf_count = 0;
}

__device__ __forceinline__ void scatter_one(int recv, int send) {
    const float4 a = __ldg(&g_xyzw[recv]);
    const float4 b = __ldg(&g_xyzw[send]);
    const float dx = a.x - b.x, dy = a.y - b.y, dz = a.z - b.z;
    const float r2 = fmaf(dx, dx, fmaf(dy, dy, dz * dz));
    if (r2 >= 64.0f) return;                       // fc == 0: dead edge
    const float rij = sqrtf(r2);
    const float s = 0.5f * (__cosf(rij * PI_OVER_CUT) + 1.0f) * b.w;
    if (s == 0.0f) return;                         // w == 0 senders

    const int pos = atomicAdd(&g_cursor[recv], 1);
    if (pos < CAP) {
        g_bucket[(long long)recv * CAP + pos] = make_float2(rij, s);
    } else {                                       // never at these degrees
        const int o = atomicAdd(&g_ovf_count, 1);
        if (o < OVF_CAP) {
            g_ovf_recv[o] = recv;
            g_ovf_rs[o] = make_float2(rij, s);
        }
    }
}

__global__ void __launch_bounds__(256) scatter_kernel(
    const int4* __restrict__ eij2,        // 2 edges per int4
    const int2* __restrict__ eij,
    int n_pairs, int n_edges)
{
    const int i = blockIdx.x * blockDim.x + threadIdx.x;
    if (i < n_pairs) {
        const int4 v = __ldg(&eij2[i]);
        scatter_one(v.x, v.y);
        scatter_one(v.z, v.w);
    }
    if (i == 0 && (n_edges & 1)) {
        const int2 t = __ldg(&eij[n_edges - 1]);
        scatter_one(t.x, t.y);
    }
}

__global__ void __launch_bounds__(256) compute_kernel(
    const float2* __restrict__ eta_mu2,
    float* __restrict__ out,
    int n_nodes)
{
    // staged table, eta prescaled: (e2 = -eta*log2e, mu). 20768 B
    __shared__ float2 tbl[N_TYPES * N_PARAMS];
    for (int i = threadIdx.x; i < N_TYPES * N_PARAMS; i += blockDim.x) {
        const float2 p = eta_mu2[i];
        tbl[i] = make_float2(-p.x * LOG2E, p.y);
    }
    __syncthreads();

    const int gid = blockIdx.x * blockDim.x + threadIdx.x;
    int node = gid >> 2;
    const int r = gid & 3;
    if (node >= n_nodes) node = n_nodes - 1;       // benign duplicate work

    const float4 a = __ldg(&g_xyzw[node]);
    const int t = (int)a.w;
    const int deg_raw = g_cursor[node];
    const int deg = deg_raw < CAP ? deg_raw : CAP;
    const float4* __restrict__ bkt4 =
        reinterpret_cast<const float4*>(g_bucket + (long long)node * CAP);

    // lane r owns params k = r, r+4, ... (6 slots; 2 padded in lanes 2,3)
    float e2[6], mu[6];
    #pragma unroll
    for (int j = 0; j < 6; j++) {
        const int k = r + 4 * j;
        const int kk = k < N_PARAMS ? k : (N_PARAMS - 1);
        const float2 p = tbl[t * N_PARAMS + kk];
        e2[j] = p.x; mu[j] = p.y;
    }
    float acc[6] = {0.f, 0.f, 0.f, 0.f, 0.f, 0.f};

    const int npair = deg >> 1;
    #pragma unroll 2
    for (int p = 0; p < npair; p++) {
        const float4 v = __ldg(&bkt4[p]);          // (r1, s1, r2, s2)
        #pragma unroll
        for (int q = 0; q < 6; q++) {
            const float d1 = v.x - mu[q];
            const float d2 = v.z - mu[q];
            acc[q] = fmaf(v.y, ex2((e2[q] * d1) * d1), acc[q]);
            acc[q] = fmaf(v.w, ex2((e2[q] * d2) * d2), acc[q]);
        }
    }
    if (deg & 1) {
        const float2 rs =
            __ldg(&reinterpret_cast<const float2*>(bkt4)[deg - 1]);
        #pragma unroll
        for (int q = 0; q < 6; q++) {
            const float d = rs.x - mu[q];
            acc[q] = fmaf(rs.y, ex2((e2[q] * d) * d), acc[q]);
        }
    }

    // CAP-overflow fold-in (never taken at these degrees; node-local, no atomics)
    if (deg_raw > CAP) {
        int count = g_ovf_count;
        if (count > OVF_CAP) count = OVF_CAP;
        for (int i = 0; i < count; i++) {
            if (g_ovf_recv[i] == node) {
                const float2 rs = g_ovf_rs[i];
                #pragma unroll
                for (int q = 0; q < 6; q++) {
                    const float d = rs.x - mu[q];
                    acc[q] = fmaf(rs.y, ex2((e2[q] * d) * d), acc[q]);
                }
            }
        }
    }

    float* o = out + (long long)node * N_PARAMS;
    #pragma unroll
    for (int j = 0; j < 6; j++) {
        const int k = r + 4 * j;
        if (k < N_PARAMS) o[k] = acc[j];           // plain coalesced store
    }
}

extern "C" void kernel_launch(void* const* d_in, const int* in_sizes, int n_in,
                              void* d_out, int out_size) {
    const int4*   z4      = (const int4*)  d_in[0];
    const float4* xyz4    = (const float4*)d_in[1];
    const int2*   eij     = (const int2*)  d_in[2];
    const int4*   eij2    = (const int4*)  d_in[2];
    const float2* eta_mu2 = (const float2*)d_in[3];
    float*        out     = (float*)d_out;

    const int n_nodes = in_sizes[0];        // 100000, divisible by 4
    const int n4 = n_nodes / 4;
    const int n_edges = in_sizes[2] / 2;
    const int n_pairs = n_edges / 2;

    pack_nodes_kernel<<<(n4 + 255) / 256, 256>>>(z4, xyz4, n4);
    scatter_kernel<<<(n_pairs + 255) / 256, 256>>>(eij2, eij, n_pairs, n_edges);

    const int threads_needed = n_nodes * 4;
    compute_kernel<<<(threads_needed + 255) / 256, 256>>>(eta_mu2, out, n_nodes);
}